// round 16
// baseline (speedup 1.0000x reference)
#include <cuda_runtime.h>

#define BATCH 128
#define DIMZ  128
#define NELEM 3072
#define MPAD  4096
#define NCHF  128      // emd chunks (one per block)
#define CWF   24       // chunk width: NCHF*CWF == NELEM
#define CS2   132      // emd transposed smem stride (floats; 16B-aligned rows)
#define ZS    129      // zsim smem row stride (odd -> conflict-free)
#define NB    128      // sort blocks
#define ZBLK  20       // zsim blocks (blocks NB..NB+ZBLK-1 of the same launch)
#define NGRID (NB + ZBLK)

// ---------------- scratch (static device globals; no allocation) -----------
__device__ float g_xs[BATCH * NELEM];          // sorted rows of x
__device__ float g_zcos[BATCH * BATCH];        // cosine similarity matrix
__device__ int   g_maxbits;                    // float-as-int max of zcos (replay-safe:
                                               // atomicMax of identical value, idempotent)
__device__ float g_part[NCHF * BATCH * BATCH]; // per-chunk EMD partial planes (8MB)
__device__ float g_bsum[NB];                   // per-block mse sums
__device__ unsigned g_cnt;                     // last-block counter (self-resetting)

// ---------------- sort primitives ------------------------------------------
__device__ __forceinline__ void cswap(float& a, float& b, bool asc) {
    float lo = fminf(a, b), hi = fmaxf(a, b);
    a = asc ? lo : hi;
    b = asc ? hi : lo;
}

// In-register bitonic stages j = jstart..1 for outer stage k (4 elems/thread).
__device__ __forceinline__ void reg_sweep(float v[4], int e0, int k, int jstart) {
    bool asc = ((e0 & k) == 0);
    for (int j = jstart; j >= 4; j >>= 1) {
        bool low = ((e0 & j) == 0);
        bool km = (low == asc);
        #pragma unroll
        for (int r = 0; r < 4; r++) {
            float o = __shfl_xor_sync(0xffffffffu, v[r], j >> 2);
            v[r] = km ? fminf(v[r], o) : fmaxf(v[r], o);
        }
    }
    if (jstart >= 2) {
        cswap(v[0], v[2], asc);
        cswap(v[1], v[3], asc);
    }
    {
        bool a0 = ((e0 & k) == 0);
        bool a1 = (((e0 + 2) & k) == 0);
        cswap(v[0], v[1], a0);
        cswap(v[2], v[3], a1);
    }
}

// All smem stages (j = K/2 .. 128) of outer stage K in ONE round trip.
template<int M, int SH, int K>
__device__ __forceinline__ void merge_group(float* s, int t) {
    if (t < (MPAD / M)) {
        int i0 = (t & 127) | ((t >> 7) << SH);
        float v[M];
        #pragma unroll
        for (int m = 0; m < M; m++) v[m] = s[i0 + (m << 7)];
        bool asc = ((i0 & K) == 0);
        #pragma unroll
        for (int jl = M >> 1; jl; jl >>= 1)
            #pragma unroll
            for (int m = 0; m < M; m++)
                if ((m & jl) == 0) cswap(v[m], v[m ^ jl], asc);
        #pragma unroll
        for (int m = 0; m < M; m++) s[i0 + (m << 7)] = v[m];
    }
}

__device__ __forceinline__ void reload_sweep_store(float* s, float v[4], int e0,
                                                   int k, bool store) {
    float4 f = *reinterpret_cast<const float4*>(&s[e0]);
    v[0] = f.x; v[1] = f.y; v[2] = f.z; v[3] = f.w;
    reg_sweep(v, e0, k, 64);
    if (store) {
        *reinterpret_cast<float4*>(&s[e0]) = make_float4(v[0], v[1], v[2], v[3]);
        __syncthreads();
    }
}

// ---------------- role bodies (called from the heterogeneous kernel) --------
__device__ void sort_body(const float* __restrict__ x, float* s, int t, int b) {
    int e0 = t * 4;

    float v[4];
    if (e0 < NELEM) {
        float4 f = *reinterpret_cast<const float4*>(x + b * NELEM + e0);
        v[0] = f.x; v[1] = f.y; v[2] = f.z; v[3] = f.w;
    } else {
        v[0] = v[1] = v[2] = v[3] = __int_as_float(0x7f800000);
    }

    for (int k = 2; k <= 128; k <<= 1)          // warp-local phase
        reg_sweep(v, e0, k, k >> 1);

    *reinterpret_cast<float4*>(&s[e0]) = make_float4(v[0], v[1], v[2], v[3]);
    __syncthreads();

    // k = 256: single smem stage j = 128, then contiguous reg sweep.
    #pragma unroll
    for (int mm = 0; mm < 2; mm++) {
        int m = t + (mm << 10);
        int i = ((m & ~127) << 1) | (m & 127);
        int li = i | 128;
        bool asc = ((i & 256) == 0);
        float a = s[i], bb = s[li];
        float lo = fminf(a, bb), hi = fmaxf(a, bb);
        s[i]  = asc ? lo : hi;
        s[li] = asc ? hi : lo;
    }
    __syncthreads();
    reload_sweep_store(s, v, e0, 256, true);

    merge_group<4, 9, 512>(s, t);
    __syncthreads();
    reload_sweep_store(s, v, e0, 512, true);

    merge_group<8, 10, 1024>(s, t);
    __syncthreads();
    reload_sweep_store(s, v, e0, 1024, true);

    merge_group<16, 11, 2048>(s, t);
    __syncthreads();
    reload_sweep_store(s, v, e0, 2048, true);

    merge_group<32, 12, 4096>(s, t);
    __syncthreads();
    reload_sweep_store(s, v, e0, 4096, false);

    if (e0 < NELEM)
        *reinterpret_cast<float4*>(g_xs + b * NELEM + e0) =
            make_float4(v[0], v[1], v[2], v[3]);
}

// zsim: 1024 threads, 8 threads per (i,j) dot (16 elems each, shfl 1/2/4).
__device__ void zsim_body(const float* __restrict__ z, float* dynsm, int t, int zb) {
    float* zs   = dynsm;               // [128][ZS]
    float* sinv = dynsm + BATCH * ZS;  // [128]
    __shared__ float redm[32];

    for (int idx = t; idx < BATCH * DIMZ; idx += 1024) {
        int r = idx >> 7, c = idx & 127;
        zs[r * ZS + c] = z[idx];
    }
    __syncthreads();

    int j = t >> 3, h = t & 7;         // 8 threads per row j
    {
        const float* zr = zs + j * ZS + h * 16;
        float acc = 0.f;
        #pragma unroll
        for (int kk = 0; kk < 16; kk++) { float v = zr[kk]; acc += v * v; }
        acc += __shfl_xor_sync(0xffffffffu, acc, 1);
        acc += __shfl_xor_sync(0xffffffffu, acc, 2);
        acc += __shfl_xor_sync(0xffffffffu, acc, 4);
        if (h == 0) sinv[j] = 1.f / fmaxf(sqrtf(acc), 1e-12f);
    }
    __syncthreads();

    float lmax = -1e30f;
    for (int i = zb; i < BATCH; i += ZBLK) {
        const float* za = zs + i * ZS + h * 16;
        const float* zc = zs + j * ZS + h * 16;
        float d = 0.f;
        #pragma unroll
        for (int kk = 0; kk < 16; kk++) d += za[kk] * zc[kk];
        d += __shfl_xor_sync(0xffffffffu, d, 1);
        d += __shfl_xor_sync(0xffffffffu, d, 2);
        d += __shfl_xor_sync(0xffffffffu, d, 4);
        float c = d * sinv[i] * sinv[j];
        if (h == 0) g_zcos[i * BATCH + j] = c;
        lmax = fmaxf(lmax, c);
    }

    #pragma unroll
    for (int o = 16; o; o >>= 1) lmax = fmaxf(lmax, __shfl_xor_sync(0xffffffffu, lmax, o));
    if ((t & 31) == 0) redm[t >> 5] = lmax;
    __syncthreads();
    if (t < 32) {
        float mx = redm[t];
        #pragma unroll
        for (int o = 16; o; o >>= 1) mx = fmaxf(mx, __shfl_xor_sync(0xffffffffu, mx, o));
        if (t == 0) atomicMax(&g_maxbits, __float_as_int(mx)); // max >= 1 > 0
    }
}

// ---------------- kernel A: heterogeneous front (sort | zsim) ---------------
extern __shared__ float dynsm[];
__global__ __launch_bounds__(1024, 1) void k_front(const float* __restrict__ z,
                                                   const float* __restrict__ x) {
    int t = threadIdx.x, b = blockIdx.x;
    if (b < NB) sort_body(x, dynsm, t, b);        // disjoint outputs, no
    else        zsim_body(z, dynsm, t, b - NB);   // cross-role dependency
}

// ---------------- kernel B: EMD plane b (CW=24 split-K) ---------------------
__global__ __launch_bounds__(1024, 1) void k_emd2() {
    __shared__ __align__(16) float st[CWF * CS2];  // transposed: st[c*CS2 + r]
    int t = threadIdx.x, b = blockIdx.x;
    int c0 = b * CWF;
    {
        int r = t >> 3, cb = (t & 7) * 3;
        const float* src = g_xs + r * NELEM + c0 + cb;
        #pragma unroll
        for (int i2 = 0; i2 < 3; i2++) st[(cb + i2) * CS2 + r] = src[i2];
    }
    __syncthreads();

    int w = t >> 5, l = t & 31;
    int txp = (l & 7) | ((w & 3) << 3);    // 0..31
    int typ = (l >> 3) | ((w >> 2) << 2);  // 0..31

    float acc[16];
    #pragma unroll
    for (int q = 0; q < 16; q++) acc[q] = 0.f;

    #pragma unroll
    for (int c = 0; c < CWF; c++) {
        float4 a4 = *reinterpret_cast<const float4*>(st + c * CS2 + 4 * typ);
        float4 b4 = *reinterpret_cast<const float4*>(st + c * CS2 + 4 * txp);
        float a[4] = {a4.x, a4.y, a4.z, a4.w};
        float bb[4] = {b4.x, b4.y, b4.z, b4.w};
        #pragma unroll
        for (int r = 0; r < 4; r++)
            #pragma unroll
            for (int q = 0; q < 4; q++) {
                float d = __fmaf_rn(bb[q], -1.f, a[r]);                     // FFMA-imm
                acc[r * 4 + q] = __fmaf_rn(fabsf(d), 1.f, acc[r * 4 + q]);  // FFMA-imm
            }
    }

    float* outp = g_part + b * (BATCH * BATCH);
    int ri = typ * 4, rj = txp * 4;
    #pragma unroll
    for (int r = 0; r < 4; r++)
        *reinterpret_cast<float4*>(outp + (ri + r) * BATCH + rj) =
            make_float4(acc[r * 4 + 0], acc[r * 4 + 1], acc[r * 4 + 2], acc[r * 4 + 3]);
}

// ---------------- kernel C: combine + MSE + final (last-block) --------------
__global__ __launch_bounds__(1024, 1) void k_mse2(float* __restrict__ out) {
    __shared__ float4 smv[32 * 32];
    __shared__ float r2[4];
    __shared__ bool last;
    int t = threadIdx.x, b = blockIdx.x;
    int w = t >> 5, l = t & 31;
    int I = b * 32 + l;                               // float4 idx in [4096]

    const float4* p4 = reinterpret_cast<const float4*>(g_part);
    float4 s4 = make_float4(0.f, 0.f, 0.f, 0.f);
    #pragma unroll
    for (int q = 0; q < 4; q++) {
        float4 p = p4[(w * 4 + q) * (BATCH * BATCH / 4) + I];
        s4.x += p.x; s4.y += p.y; s4.z += p.z; s4.w += p.w;
    }
    smv[w * 32 + l] = s4;
    __syncthreads();
    if (w < 8) {
        float4 a = smv[w * 32 + l];
        float4 b1 = smv[(w + 8) * 32 + l];
        float4 b2 = smv[(w + 16) * 32 + l];
        float4 b3 = smv[(w + 24) * 32 + l];
        a.x += b1.x + b2.x + b3.x;
        a.y += b1.y + b2.y + b3.y;
        a.z += b1.z + b2.z + b3.z;
        a.w += b1.w + b2.w + b3.w;
        smv[w * 32 + l] = a;
    }
    __syncthreads();
    float vv = 0.f;
    if (w == 0) {
        float4 a = smv[l];
        #pragma unroll
        for (int g = 1; g < 8; g++) {
            float4 p = smv[g * 32 + l];
            a.x += p.x; a.y += p.y; a.z += p.z; a.w += p.w;
        }
        float4 zc = reinterpret_cast<const float4*>(g_zcos)[I];
        float gmax = __int_as_float(g_maxbits);
        const float inv = 1.f / (float)NELEM;
        float dx = a.x * inv + zc.x - gmax;
        float dy = a.y * inv + zc.y - gmax;
        float dz = a.z * inv + zc.z - gmax;
        float dw = a.w * inv + zc.w - gmax;
        vv = dx * dx + dy * dy + dz * dz + dw * dw;
        #pragma unroll
        for (int o = 16; o; o >>= 1) vv += __shfl_xor_sync(0xffffffffu, vv, o);
    }
    if (t == 0) {
        g_bsum[b] = vv;
        __threadfence();
        unsigned c = atomicAdd(&g_cnt, 1u);
        last = (c == (unsigned)(NB - 1));
    }
    __syncthreads();
    if (last) {
        if (t < NB) {
            float wv = g_bsum[t];
            #pragma unroll
            for (int o = 16; o; o >>= 1) wv += __shfl_xor_sync(0xffffffffu, wv, o);
            if ((t & 31) == 0) r2[t >> 5] = wv;
        }
        __syncthreads();
        if (t == 0) {
            out[0] = (r2[0] + r2[1] + r2[2] + r2[3]) * (1.f / (float)(BATCH * BATCH));
            g_cnt = 0u;  // self-reset for next graph replay
        }
    }
}

// ---------------- launch ----------------------------------------------------
extern "C" void kernel_launch(void* const* d_in, const int* in_sizes, int n_in,
                              void* d_out, int out_size) {
    const float* z = (const float*)d_in[0];
    const float* x = (const float*)d_in[1];
    if (n_in >= 2 && in_sizes[0] == BATCH * NELEM) {  // defensive swap
        const float* tmp = z; z = x; x = tmp;
    }

    int smem = (BATCH * ZS + BATCH) * (int)sizeof(float);  // 66560 B (zsim role max)
    static int attr_set = 0;
    if (!attr_set) {
        cudaFuncSetAttribute(k_front, cudaFuncAttributeMaxDynamicSharedMemorySize, smem);
        attr_set = 1;
    }

    k_front<<<NGRID, 1024, smem>>>(z, x);
    k_emd2<<<NB, 1024>>>();
    k_mse2<<<NB, 1024>>>((float*)d_out);
}